// round 16
// baseline (speedup 1.0000x reference)
#include <cuda_runtime.h>

#define T_    16384
#define TILE  256              // elements per warp-tile (8 per lane)
#define SPAN  2048             // output elements per warp
#define SPANS (T_ / SPAN)      // 8 warps per row
#define MT    (SPAN / TILE)    // 8 main tiles per warp (processed in pairs)
#define WPC   4
#define FULL  0xffffffffu

struct Ser { float b, w1, w2, w3, w4, w5, w6, pw, iw1; };

__device__ __forceinline__ Ser make_ser(float b, int lane) {
    Ser s; s.b = b;
    float b2 = b * b, b4 = b2 * b2;
    s.w1 = b4 * b4;          // b^8
    s.w2 = s.w1 * s.w1;      // b^16
    s.w3 = s.w2 * s.w2;      // b^32
    s.w4 = s.w3 * s.w3;      // b^64
    s.w5 = s.w4 * s.w4;      // b^128
    s.w6 = s.w5 * s.w5;      // b^256 (whole-tile carry weight)
    s.iw1 = __fdividef(1.f, s.w1);   // b^-8 (entry-prefix from own Bv)
    float pw = 1.f, p = s.w1;
#pragma unroll
    for (int k = 0; k < 5; ++k) { if (lane & (1 << k)) pw *= p; p *= p; }
    s.pw = pw;               // b^(8*lane)
    return s;
}

// Compose (7 FMA) + 5-step Kogge-Stone. Outputs: B0 = own-segment value,
// Bv = inclusive-across-lanes, tot = lane31 value. Entry prefix is
// (Bv - B0) * b^-8 (== shfl_up(Bv,1); exactly 0 on lane 0). No reconstruct.
__device__ __forceinline__ void composeKS(const Ser s, const float v[8],
                                          float& B0o, float& Bvo, float& toto,
                                          int lane)
{
    float B0 = v[0];
#pragma unroll
    for (int i = 1; i < 8; ++i) B0 = fmaf(s.b, B0, v[i]);
    float Bv = B0, t;
    t = __shfl_up_sync(FULL, Bv, 1);  if (lane >= 1)  Bv = fmaf(s.w1, t, Bv);
    t = __shfl_up_sync(FULL, Bv, 2);  if (lane >= 2)  Bv = fmaf(s.w2, t, Bv);
    t = __shfl_up_sync(FULL, Bv, 4);  if (lane >= 4)  Bv = fmaf(s.w3, t, Bv);
    t = __shfl_up_sync(FULL, Bv, 8);  if (lane >= 8)  Bv = fmaf(s.w4, t, Bv);
    t = __shfl_up_sync(FULL, Bv, 16); if (lane >= 16) Bv = fmaf(s.w5, t, Bv);
    toto = __shfl_sync(FULL, Bv, 31);
    B0o = B0; Bvo = Bv;
}

__device__ __forceinline__ void load8(float v[8], const float* __restrict__ p) {
    const float4 a = *(const float4*)p;
    const float4 b = *(const float4*)(p + 4);
    v[0]=a.x; v[1]=a.y; v[2]=a.z; v[3]=a.w;
    v[4]=b.x; v[5]=b.y; v[6]=b.z; v[7]=b.w;
}

__global__ __launch_bounds__(32 * WPC)
void macd_scan(const float* __restrict__ x,
               const int* __restrict__ ps_, const int* __restrict__ pl_,
               const int* __restrict__ pg_,
               float* __restrict__ out, int B)
{
    const int lane = threadIdx.x & 31;
    const int w    = blockIdx.x * WPC + (threadIdx.x >> 5);
    const int row  = w / SPANS;
    const int span = w - row * SPANS;
    if (row >= B) return;

    const float a_s = 2.f / (float)(ps_[0] + 1), b_s = 1.f - a_s;
    const float a_l = 2.f / (float)(pl_[0] + 1), b_l = 1.f - a_l;
    const float a_g = 2.f / (float)(pg_[0] + 1), b_g = 1.f - a_g;
    const Ser ss = make_ser(b_s, lane);
    const Ser sl = make_ser(b_l, lane);
    const Ser sg = make_ser(b_g, lane);

    const size_t rbase = (size_t)row * T_;
    const int    off0  = span * SPAN;
    const size_t N     = (size_t)B * T_;
    const float* __restrict__ xp = x + rbase;
    float* __restrict__ om = out;
    float* __restrict__ og = out + N;
    float* __restrict__ oh = out + 2 * N;

    // Unnormalized carries: F = b*F + input (inputs: x for s/l, m for g).
    // Outputs: ema_s = a_s*Fs, macd m = a_s*Fs - a_l*Fl, sig = a_g*Fg.
    float Fs, Fl, Fg;

    if (span == 0) {
        // Exact init: F = x0/a gives y_0 = x_0 (to ulp); sig starts 0.
        const float x0 = __ldg(xp);
        Fs = x0 * __fdividef(1.f, a_s);
        Fl = x0 * __fdividef(1.f, a_l);
        Fg = 0.f;
    } else {
        // Carry-only warmup over [off0-256, off0): three KS scans of RAW x;
        // the g-carry follows from partial fractions (validated R10/R14),
        // scaled to unnormalized units (divide K's by a_g).
        const float r_s = __fdividef(1.f, b_g - b_s);
        const float r_l = __fdividef(1.f, b_g - b_l);
        const float Kp_s = -a_s * b_s * r_s;
        const float Kp_l =  a_l * b_l * r_l;
        const float Kp_g =  b_g * (a_s * r_s - a_l * r_l);
        const float sg_c = __fdividef(b_s * r_s - b_l * r_l,
                                      b_g * (a_s * r_s - a_l * r_l));

        float wv[8];
        load8(wv, xp + (off0 - TILE) + lane * 8);
        const float x0 = __shfl_sync(FULL, wv[0], 0);
        float FsW = x0 * __fdividef(1.f, a_s);
        float FlW = x0 * __fdividef(1.f, a_l);
        float FgW = x0 * sg_c;
        float B0, Bv, tot;
        composeKS(ss, wv, B0, Bv, tot, lane); FsW = fmaf(ss.w6, FsW, tot);
        composeKS(sl, wv, B0, Bv, tot, lane); FlW = fmaf(sl.w6, FlW, tot);
        composeKS(sg, wv, B0, Bv, tot, lane); FgW = fmaf(sg.w6, FgW, tot);
        Fs = FsW;
        Fl = FlW;
        Fg = fmaf(Kp_s, FsW, fmaf(Kp_l, FlW, Kp_g * FgW));
    }

#pragma unroll 1
    for (int t = 0; t < MT; t += 2) {
        const size_t baseA = rbase + (size_t)off0 + t * TILE + lane * 8;
        const size_t baseB = baseA + TILE;
        float xa[8], xb[8];
        load8(xa, x + baseA);            // 4 LDG.128 batched -> MLP 4
        load8(xb, x + baseB);

        // Four independent compose+KS chains (s/l x A/B) interleave.
        float B0, Bv, tot;
        float eAs, eAl, eBs, eBl;
        composeKS(ss, xa, B0, Bv, tot, lane);
        eAs = fmaf(ss.pw, Fs, (Bv - B0) * ss.iw1);
        Fs  = fmaf(ss.w6, Fs, tot);
        composeKS(sl, xa, B0, Bv, tot, lane);
        eAl = fmaf(sl.pw, Fl, (Bv - B0) * sl.iw1);
        Fl  = fmaf(sl.w6, Fl, tot);
        composeKS(ss, xb, B0, Bv, tot, lane);
        eBs = fmaf(ss.pw, Fs, (Bv - B0) * ss.iw1);
        Fs  = fmaf(ss.w6, Fs, tot);
        composeKS(sl, xb, B0, Bv, tot, lane);
        eBl = fmaf(sl.pw, Fl, (Bv - B0) * sl.iw1);
        Fl  = fmaf(sl.w6, Fl, tot);

        // Reconstruct A -> macd values (xa dies here).
        float mA[8];
        {
            float es = eAs, el = eAl;
#pragma unroll
            for (int i = 0; i < 8; ++i) {
                es = fmaf(b_s, es, xa[i]);
                el = fmaf(b_l, el, xa[i]);
                mA[i] = fmaf(a_s, es, -(a_l * el));
            }
        }
        // Signal scan A (input = mA); B's reconstruct can overlap this KS.
        composeKS(sg, mA, B0, Bv, tot, lane);
        float egA = fmaf(sg.pw, Fg, (Bv - B0) * sg.iw1);
        Fg = fmaf(sg.w6, Fg, tot);

        // Reconstruct B -> macd values (independent of A's signal chain).
        float mB[8];
        {
            float es = eBs, el = eBl;
#pragma unroll
            for (int i = 0; i < 8; ++i) {
                es = fmaf(b_s, es, xb[i]);
                el = fmaf(b_l, el, xb[i]);
                mB[i] = fmaf(a_s, es, -(a_l * el));
            }
        }

        // Signal reconstruct + stores for A.
        {
            float eg = egA;
            float g0, g1, g2, g3;
            eg = fmaf(b_g, eg, mA[0]); g0 = a_g * eg;
            eg = fmaf(b_g, eg, mA[1]); g1 = a_g * eg;
            eg = fmaf(b_g, eg, mA[2]); g2 = a_g * eg;
            eg = fmaf(b_g, eg, mA[3]); g3 = a_g * eg;
            *(float4*)(om + baseA) = make_float4(mA[0], mA[1], mA[2], mA[3]);
            *(float4*)(og + baseA) = make_float4(g0, g1, g2, g3);
            *(float4*)(oh + baseA) = make_float4(mA[0]-g0, mA[1]-g1, mA[2]-g2, mA[3]-g3);
            eg = fmaf(b_g, eg, mA[4]); g0 = a_g * eg;
            eg = fmaf(b_g, eg, mA[5]); g1 = a_g * eg;
            eg = fmaf(b_g, eg, mA[6]); g2 = a_g * eg;
            eg = fmaf(b_g, eg, mA[7]); g3 = a_g * eg;
            *(float4*)(om + baseA + 4) = make_float4(mA[4], mA[5], mA[6], mA[7]);
            *(float4*)(og + baseA + 4) = make_float4(g0, g1, g2, g3);
            *(float4*)(oh + baseA + 4) = make_float4(mA[4]-g0, mA[5]-g1, mA[6]-g2, mA[7]-g3);
        }

        // Signal scan B + reconstruct + stores.
        composeKS(sg, mB, B0, Bv, tot, lane);
        float egB = fmaf(sg.pw, Fg, (Bv - B0) * sg.iw1);
        Fg = fmaf(sg.w6, Fg, tot);
        {
            float eg = egB;
            float g0, g1, g2, g3;
            eg = fmaf(b_g, eg, mB[0]); g0 = a_g * eg;
            eg = fmaf(b_g, eg, mB[1]); g1 = a_g * eg;
            eg = fmaf(b_g, eg, mB[2]); g2 = a_g * eg;
            eg = fmaf(b_g, eg, mB[3]); g3 = a_g * eg;
            *(float4*)(om + baseB) = make_float4(mB[0], mB[1], mB[2], mB[3]);
            *(float4*)(og + baseB) = make_float4(g0, g1, g2, g3);
            *(float4*)(oh + baseB) = make_float4(mB[0]-g0, mB[1]-g1, mB[2]-g2, mB[3]-g3);
            eg = fmaf(b_g, eg, mB[4]); g0 = a_g * eg;
            eg = fmaf(b_g, eg, mB[5]); g1 = a_g * eg;
            eg = fmaf(b_g, eg, mB[6]); g2 = a_g * eg;
            eg = fmaf(b_g, eg, mB[7]); g3 = a_g * eg;
            *(float4*)(om + baseB + 4) = make_float4(mB[4], mB[5], mB[6], mB[7]);
            *(float4*)(og + baseB + 4) = make_float4(g0, g1, g2, g3);
            *(float4*)(oh + baseB + 4) = make_float4(mB[4]-g0, mB[5]-g1, mB[6]-g2, mB[7]-g3);
        }
    }
}

extern "C" void kernel_launch(void* const* d_in, const int* in_sizes, int n_in,
                              void* d_out, int out_size)
{
    const float* x  = (const float*)d_in[0];
    const int*   ps = (const int*)d_in[1];
    const int*   pl = (const int*)d_in[2];
    const int*   pg = (const int*)d_in[3];

    const int B = in_sizes[0] / T_;
    float* out = (float*)d_out;

    const int total_warps = B * SPANS;
    const int blocks = (total_warps + WPC - 1) / WPC;

    macd_scan<<<blocks, 32 * WPC>>>(x, ps, pl, pg, out, B);
}